// round 1
// baseline (speedup 1.0000x reference)
#include <cuda_runtime.h>

// CanonConv: out[b,t,c] = x[b,t,c] + bias[c] + sum_{k=0..3} w[c,k] * x[b, t+k-3, c]
// x: (B=4, T=4096, C=2048) fp32, row-major (b,t,c). weight: (C,4). bias: (C,).
//
// Memory-bound: 128MB in + 128MB out. Strategy: one thread = one float4 channel
// group for a strip of S=64 timesteps, sliding-window in registers so each x
// element is loaded exactly once (plus a 3-row halo per strip).

#define BB 4
#define TT 4096
#define CC 2048
#define CV (CC / 4)       // 512 float4 channel-vectors per row
#define S  64             // timesteps per block strip
#define TPB 128           // threads per block (covers 128 cvecs)

__global__ __launch_bounds__(TPB) void canonconv_kernel(
    const float* __restrict__ x,
    const float* __restrict__ w,      // (C, 4)
    const float* __restrict__ bias,   // (C,)
    float* __restrict__ out)
{
    const int cvec = blockIdx.y * TPB + threadIdx.x;   // 0..511
    const int c    = cvec * 4;
    const int b    = blockIdx.z;
    const int t0   = blockIdx.x * S;

    const float4* __restrict__ x4 = reinterpret_cast<const float4*>(x);
    float4* __restrict__ o4       = reinterpret_cast<float4*>(out);

    // per-channel weight rows: wr[j] = (w[c+j,0], w[c+j,1], w[c+j,2], w[c+j,3])
    const float4* __restrict__ w4 = reinterpret_cast<const float4*>(w);
    const float4 wr0 = w4[c + 0];
    const float4 wr1 = w4[c + 1];
    const float4 wr2 = w4[c + 2];
    const float4 wr3 = w4[c + 3];
    const float4 bi  = reinterpret_cast<const float4*>(bias)[cvec];

    const long rowstride = CV;
    long base = ((long)b * TT) * CV + cvec;

    const float4 zero = make_float4(0.f, 0.f, 0.f, 0.f);
    // sliding window: x at t0-3, t0-2, t0-1
    float4 xm3 = (t0 >= 3) ? x4[base + (long)(t0 - 3) * rowstride] : zero;
    float4 xm2 = (t0 >= 2) ? x4[base + (long)(t0 - 2) * rowstride] : zero;
    float4 xm1 = (t0 >= 1) ? x4[base + (long)(t0 - 1) * rowstride] : zero;

    long idx = base + (long)t0 * rowstride;

#pragma unroll 4
    for (int i = 0; i < S; i++) {
        const float4 xc = x4[idx];
        float4 r;
        // r = xc + bias + w0*x[t-3] + w1*x[t-2] + w2*x[t-1] + w3*x[t]
        r.x = fmaf(xm3.x, wr0.x, fmaf(xm2.x, wr0.y, fmaf(xm1.x, wr0.z, fmaf(xc.x, wr0.w, xc.x + bi.x))));
        r.y = fmaf(xm3.y, wr1.x, fmaf(xm2.y, wr1.y, fmaf(xm1.y, wr1.z, fmaf(xc.y, wr1.w, xc.y + bi.y))));
        r.z = fmaf(xm3.z, wr2.x, fmaf(xm2.z, wr2.y, fmaf(xm1.z, wr2.z, fmaf(xc.z, wr2.w, xc.z + bi.z))));
        r.w = fmaf(xm3.w, wr3.x, fmaf(xm2.w, wr3.y, fmaf(xm1.w, wr3.z, fmaf(xc.w, wr3.w, xc.w + bi.w))));
        o4[idx] = r;
        xm3 = xm2; xm2 = xm1; xm1 = xc;
        idx += rowstride;
    }
}

extern "C" void kernel_launch(void* const* d_in, const int* in_sizes, int n_in,
                              void* d_out, int out_size)
{
    const float* x    = (const float*)d_in[0];
    const float* w    = (const float*)d_in[1];
    const float* bias = (const float*)d_in[2];
    float* out        = (float*)d_out;

    dim3 grid(TT / S, CV / TPB, BB);   // (64, 4, 4)
    dim3 block(TPB);
    canonconv_kernel<<<grid, block>>>(x, w, bias, out);
}

// round 3
// speedup vs baseline: 1.2165x; 1.2165x over previous
#include <cuda_runtime.h>

// CanonConv: out[b,t,c] = x[b,t,c] + bias[c] + sum_{k=0..3} w[c,k] * x[b, t+k-3, c]
// x: (B=4, T=4096, C=2048) fp32, row-major. weight: (C,4). bias: (C,).
//
// R1: latency-limited at S=64 (occ 40%, MLP 4, DRAM 57%).
// R2: S=32 (2x warps in flight) + unroll 8 (2x MLP) + int indexing + streaming stores.

#define BB 4
#define TT 4096
#define CC 2048
#define CV (CC / 4)       // 512 float4 channel-vectors per row
#define S  32             // timesteps per block strip
#define TPB 128           // threads per block (covers 128 cvecs)

__global__ __launch_bounds__(TPB) void canonconv_kernel(
    const float* __restrict__ x,
    const float* __restrict__ w,      // (C, 4)
    const float* __restrict__ bias,   // (C,)
    float* __restrict__ out)
{
    const int cvec = blockIdx.y * TPB + threadIdx.x;   // 0..511
    const int c    = cvec * 4;
    const int b    = blockIdx.z;
    const int t0   = blockIdx.x * S;

    const float4* __restrict__ x4 = reinterpret_cast<const float4*>(x);
    float4* __restrict__ o4       = reinterpret_cast<float4*>(out);

    // per-channel weight rows: wr[j] = (w[c+j,0..3])
    const float4* __restrict__ w4 = reinterpret_cast<const float4*>(w);
    const float4 wr0 = w4[c + 0];
    const float4 wr1 = w4[c + 1];
    const float4 wr2 = w4[c + 2];
    const float4 wr3 = w4[c + 3];
    const float4 bi  = reinterpret_cast<const float4*>(bias)[cvec];

    // all indices fit comfortably in int: max 4*4096*512 = 8.4M float4s
    int idx = (b * TT + t0) * CV + cvec;

    const float4 zero = make_float4(0.f, 0.f, 0.f, 0.f);
    // sliding window: x at t0-3, t0-2, t0-1 (t0 is a multiple of S)
    float4 xm3 = (t0 >= 3) ? x4[idx - 3 * CV] : zero;
    float4 xm2 = (t0 >= 2) ? x4[idx - 2 * CV] : zero;
    float4 xm1 = (t0 >= 1) ? x4[idx - 1 * CV] : zero;

#pragma unroll 8
    for (int i = 0; i < S; i++) {
        const float4 xc = x4[idx];
        float4 r;
        r.x = fmaf(xm3.x, wr0.x, fmaf(xm2.x, wr0.y, fmaf(xm1.x, wr0.z, fmaf(xc.x, wr0.w, xc.x + bi.x))));
        r.y = fmaf(xm3.y, wr1.x, fmaf(xm2.y, wr1.y, fmaf(xm1.y, wr1.z, fmaf(xc.y, wr1.w, xc.y + bi.y))));
        r.z = fmaf(xm3.z, wr2.x, fmaf(xm2.z, wr2.y, fmaf(xm1.z, wr2.z, fmaf(xc.z, wr2.w, xc.z + bi.z))));
        r.w = fmaf(xm3.w, wr3.x, fmaf(xm2.w, wr3.y, fmaf(xm1.w, wr3.z, fmaf(xc.w, wr3.w, xc.w + bi.w))));
        __stcs(&o4[idx], r);   // streaming store: don't pollute L2
        xm3 = xm2; xm2 = xm1; xm1 = xc;
        idx += CV;
    }
}

extern "C" void kernel_launch(void* const* d_in, const int* in_sizes, int n_in,
                              void* d_out, int out_size)
{
    const float* x    = (const float*)d_in[0];
    const float* w    = (const float*)d_in[1];
    const float* bias = (const float*)d_in[2];
    float* out        = (float*)d_out;

    dim3 grid(TT / S, CV / TPB, BB);   // (128, 4, 4) = 2048 CTAs
    dim3 block(TPB);
    canonconv_kernel<<<grid, block>>>(x, w, bias, out);
}

// round 8
// speedup vs baseline: 1.2281x; 1.0095x over previous
#include <cuda_runtime.h>

// CanonConv: out[b,t,c] = x[b,t,c] + bias[c] + sum_{k=0..3} w[c,k] * x[b, t+k-3, c]
// x: (B=4, T=4096, C=2048) fp32, row-major. weight: (C,4). bias: (C,).
//
// R1: latency-limited at S=64 (occ 40%, MLP 4, DRAM 57%).   -> 50.8us kernel
// R2: S=32, unroll 8, int idx, __stcs. DRAM 70.8%, occ still 40.5% (reg-capped). -> 40.3us
// R3: S=16 fully unrolled + launch_bounds min-9-CTAs (regs 62->56, 36 warps/SM).
// R4: container infra failure — resubmitting R3 design for its measurement.

#define BB 4
#define TT 4096
#define CC 2048
#define CV (CC / 4)       // 512 float4 channel-vectors per row
#define S  16             // timesteps per block strip
#define TPB 128           // threads per block (covers 128 cvecs)

__global__ __launch_bounds__(TPB, 9) void canonconv_kernel(
    const float* __restrict__ x,
    const float* __restrict__ w,      // (C, 4)
    const float* __restrict__ bias,   // (C,)
    float* __restrict__ out)
{
    const int cvec = blockIdx.y * TPB + threadIdx.x;   // 0..511
    const int c    = cvec * 4;
    const int b    = blockIdx.z;
    const int t0   = blockIdx.x * S;

    const float4* __restrict__ x4 = reinterpret_cast<const float4*>(x);
    float4* __restrict__ o4       = reinterpret_cast<float4*>(out);

    // per-channel weight rows: wr[j] = (w[c+j,0..3])
    const float4* __restrict__ w4 = reinterpret_cast<const float4*>(w);
    const float4 wr0 = w4[c + 0];
    const float4 wr1 = w4[c + 1];
    const float4 wr2 = w4[c + 2];
    const float4 wr3 = w4[c + 3];
    const float4 bi  = reinterpret_cast<const float4*>(bias)[cvec];

    // max index 4*4096*512 = 8.4M float4s -> fits int
    int idx = (b * TT + t0) * CV + cvec;

    const float4 zero = make_float4(0.f, 0.f, 0.f, 0.f);
    // sliding window: x at t0-3, t0-2, t0-1 (t0 is a multiple of S)
    float4 xm3 = (t0 >= 3) ? x4[idx - 3 * CV] : zero;
    float4 xm2 = (t0 >= 2) ? x4[idx - 2 * CV] : zero;
    float4 xm1 = (t0 >= 1) ? x4[idx - 1 * CV] : zero;

#pragma unroll
    for (int i = 0; i < S; i++) {
        const float4 xc = x4[idx];
        float4 r;
        r.x = fmaf(xm3.x, wr0.x, fmaf(xm2.x, wr0.y, fmaf(xm1.x, wr0.z, fmaf(xc.x, wr0.w, xc.x + bi.x))));
        r.y = fmaf(xm3.y, wr1.x, fmaf(xm2.y, wr1.y, fmaf(xm1.y, wr1.z, fmaf(xc.y, wr1.w, xc.y + bi.y))));
        r.z = fmaf(xm3.z, wr2.x, fmaf(xm2.z, wr2.y, fmaf(xm1.z, wr2.z, fmaf(xc.z, wr2.w, xc.z + bi.z))));
        r.w = fmaf(xm3.w, wr3.x, fmaf(xm2.w, wr3.y, fmaf(xm1.w, wr3.z, fmaf(xc.w, wr3.w, xc.w + bi.w))));
        __stcs(&o4[idx], r);   // streaming store: don't pollute L2
        xm3 = xm2; xm2 = xm1; xm1 = xc;
        idx += CV;
    }
}

extern "C" void kernel_launch(void* const* d_in, const int* in_sizes, int n_in,
                              void* d_out, int out_size)
{
    const float* x    = (const float*)d_in[0];
    const float* w    = (const float*)d_in[1];
    const float* bias = (const float*)d_in[2];
    float* out        = (float*)d_out;

    dim3 grid(TT / S, CV / TPB, BB);   // (256, 4, 4) = 4096 CTAs
    dim3 block(TPB);
    canonconv_kernel<<<grid, block>>>(x, w, bias, out);
}